// round 15
// baseline (speedup 1.0000x reference)
#include <cuda_runtime.h>
#include <cstddef>

// Problem constants (fixed by setup_inputs)
#define B_   32
#define CIN  256
#define COUT 512
#define H_   64
#define W_   64
#define HW   (H_*W_)          // 4096
#define GROUPS 9
#define IN_CPG 28             // 252 channels used, 28 per group
#define OUT_CPG 56            // 504 channels, 56 per group; 504..511 -> group 4

#define NBLK 608              // 4/SM x 152 (GB300); excess blocks drain & exit safely
#define WEFF_TASKS 576        // warp per (o,g), 8 warps per task, tasks [0, 576)
#define GSUM_TASKS 1152       // tasks [576, 1728), batch-major (36 per batch)
#define PH1_TASKS  (WEFF_TASKS + GSUM_TASKS)
#define TASKS_PER_BATCH 36    // 9 groups x 4 quarter-planes
#define PW_TASKS (B_ * H_ * 2)  // 4096 half-row tasks (o-split), batch-major

#define WSTRIDE 20            // floats per o-row in w_dup2 (9 dup pairs + pad, 80B)

// Scratch + pipeline state (all zero-init; reset by last departer each launch)
__device__ float g_s[B_ * GROUPS * HW];
__device__ float g_we[COUT * GROUPS];
__device__ int g_t1, g_t2, g_weff_cnt, g_dep;
__device__ int g_ready[B_];

__global__ __launch_bounds__(256, 4) void shiftconv_fused(
    const float4* __restrict__ x4, const float* __restrict__ wp,
    float* __restrict__ y)
{
    __shared__ float w_dup2[COUT * WSTRIDE];             // 40,960 B
    __shared__ float s_sh[GROUPS][W_ + 2];               // 2,376 B
    __shared__ int task_sh;
    const int tid = threadIdx.x;

    // ================= Phase 1: pop prep tasks =================
    for (;;) {
        if (tid == 0) task_sh = atomicAdd(&g_t1, 1);
        __syncthreads();
        const int t = task_sh;
        __syncthreads();                                 // protect task_sh reuse
        if (t >= PH1_TASKS) break;

        if (t < WEFF_TASKS) {
            // W_eff: 8 warps per task, warp per (o,g), shuffle reduce
            const int warp = t * 8 + (tid >> 5);
            const int lane = tid & 31;
            const int o = warp / GROUPS, g = warp % GROUPS;
            const float* row = wp + (size_t)o * COUT;
            float s = 0.f;
            if (lane < IN_CPG)
                s = row[g * OUT_CPG + lane] + row[g * OUT_CPG + 28 + lane];
            if (g == 4 && lane < 8)
                s += row[504 + lane];
#pragma unroll
            for (int off = 16; off > 0; off >>= 1)
                s += __shfl_xor_sync(0xffffffffu, s, off);
            if (lane == 0) g_we[warp] = s;
            __threadfence();                             // release
            __syncthreads();
            if (tid == 0) atomicAdd(&g_weff_cnt, 1);
        } else {
            // gsum quarter-plane: j in [0,1152), one (b,g) quarter each
            const int j   = t - WEFF_TASKS;
            const int idx = j * 256 + tid;
            const int hw4 = idx & (HW / 4 - 1);
            const int tt  = idx >> 10;                   // b*9+g
            const int b = tt / GROUPS, g = tt % GROUPS;
            const float4* p = x4 + ((size_t)(b * CIN + g * IN_CPG) << 10) + hw4;
            float4 a = make_float4(0.f, 0.f, 0.f, 0.f);
#pragma unroll
            for (int k = 0; k < IN_CPG; k++) {
                float4 v = __ldcs(p + ((size_t)k << 10));
                a.x += v.x; a.y += v.y; a.z += v.z; a.w += v.w;
            }
            reinterpret_cast<float4*>(g_s)[(size_t)tt * (HW / 4) + hw4] = a;
            __threadfence();                             // release
            __syncthreads();
            if (tid == 0) atomicAdd(&g_ready[j / TASKS_PER_BATCH], 1);
        }
    }

    // ============ Transition: wait weff, stage weights once ============
    if (tid == 0) {
        while (*(volatile int*)&g_weff_cnt < WEFF_TASKS) __nanosleep(64);
    }
    __syncthreads();
    __threadfence();                                     // acquire side
    for (int i = tid; i < COUT * GROUPS; i += 256) {
        int o = i / GROUPS, g = i - o * GROUPS;
        float v = __ldcg(&g_we[i]);                      // L2 read (no L1 window)
        w_dup2[o * WSTRIDE + 2 * g]     = v;
        w_dup2[o * WSTRIDE + 2 * g + 1] = v;
    }
    for (int i = tid; i < GROUPS * (W_ + 2); i += 256)   // halo zeros
        (&s_sh[0][0])[i] = 0.f;
    // pop-sync below covers visibility of w_dup2/s_sh before first use

    const int w0  = (tid & 15) * 4;
    const int och = tid >> 4;                            // 0..15

    // ========== Phase 2: pop pw half-row tasks (o-split) ==========
    // r: [0,4096). b=r>>7, h=(r>>1)&63, half=r&1 -> oo in [half*16, half*16+16)
    for (;;) {
        if (tid == 0) {
            int r = atomicAdd(&g_t2, 1);
            if (r < PW_TASKS) {
                int rb = r >> 7;
                while (*(volatile int*)&g_ready[rb] < TASKS_PER_BATCH)
                    __nanosleep(64);
            }
            task_sh = r;
        }
        __syncthreads();
        const int r = task_sh;
        __syncthreads();                                 // protect task_sh + s_sh reuse
        if (r >= PW_TASKS) break;
        const int b = r >> 7, h = (r >> 1) & 63;
        const int oob = (r & 1) * 16;                    // oo base: 0 or 16
        __threadfence();                                 // acquire for g_s

        // stage the single s row each group needs (unconditional: zeros for OOB)
        for (int i = tid; i < GROUPS * W_; i += 256) {
            int g = i >> 6, wc = i & 63;
            int hp = h + g / 3 - 1;
            s_sh[g][wc + 1] = ((unsigned)hp < (unsigned)H_)
                ? __ldcg(&g_s[((size_t)(b * GROUPS + g) << 12) + (hp << 6) + wc])
                : 0.f;
        }
        __syncthreads();

        // pack shifted s pixel pairs: idx w0+dx+1 = w0 + g%3
        unsigned long long sv2[GROUPS][2];
#pragma unroll
        for (int g = 0; g < GROUPS; g++) {
            const float* rr = &s_sh[g][w0 + (g % 3)];
            asm("mov.b64 %0, {%1, %2};" : "=l"(sv2[g][0]) : "f"(rr[0]), "f"(rr[1]));
            asm("mov.b64 %0, {%1, %2};" : "=l"(sv2[g][1]) : "f"(rr[2]), "f"(rr[3]));
        }

        float4* yp = reinterpret_cast<float4*>(
            y + ((size_t)b * COUT + och) * HW + h * W_ + w0);
#pragma unroll 4
        for (int oi = 0; oi < 16; oi++) {
            const int oo = oob + oi;
            const int o = oo * 16 + och;
            const float* wrow = &w_dup2[o * WSTRIDE];
            ulonglong2 wA = *reinterpret_cast<const ulonglong2*>(wrow);      // g0,g1
            ulonglong2 wB = *reinterpret_cast<const ulonglong2*>(wrow + 4);  // g2,g3
            ulonglong2 wC = *reinterpret_cast<const ulonglong2*>(wrow + 8);  // g4,g5
            ulonglong2 wD = *reinterpret_cast<const ulonglong2*>(wrow + 12); // g6,g7
            unsigned long long wE =
                *reinterpret_cast<const unsigned long long*>(wrow + 16);     // g8

            unsigned long long a0 = 0ull, a1 = 0ull;
            asm("fma.rn.f32x2 %0, %1, %2, %0;" : "+l"(a0) : "l"(wA.x), "l"(sv2[0][0]));
            asm("fma.rn.f32x2 %0, %1, %2, %0;" : "+l"(a1) : "l"(wA.x), "l"(sv2[0][1]));
            asm("fma.rn.f32x2 %0, %1, %2, %0;" : "+l"(a0) : "l"(wA.y), "l"(sv2[1][0]));
            asm("fma.rn.f32x2 %0, %1, %2, %0;" : "+l"(a1) : "l"(wA.y), "l"(sv2[1][1]));
            asm("fma.rn.f32x2 %0, %1, %2, %0;" : "+l"(a0) : "l"(wB.x), "l"(sv2[2][0]));
            asm("fma.rn.f32x2 %0, %1, %2, %0;" : "+l"(a1) : "l"(wB.x), "l"(sv2[2][1]));
            asm("fma.rn.f32x2 %0, %1, %2, %0;" : "+l"(a0) : "l"(wB.y), "l"(sv2[3][0]));
            asm("fma.rn.f32x2 %0, %1, %2, %0;" : "+l"(a1) : "l"(wB.y), "l"(sv2[3][1]));
            asm("fma.rn.f32x2 %0, %1, %2, %0;" : "+l"(a0) : "l"(wC.x), "l"(sv2[4][0]));
            asm("fma.rn.f32x2 %0, %1, %2, %0;" : "+l"(a1) : "l"(wC.x), "l"(sv2[4][1]));
            asm("fma.rn.f32x2 %0, %1, %2, %0;" : "+l"(a0) : "l"(wC.y), "l"(sv2[5][0]));
            asm("fma.rn.f32x2 %0, %1, %2, %0;" : "+l"(a1) : "l"(wC.y), "l"(sv2[5][1]));
            asm("fma.rn.f32x2 %0, %1, %2, %0;" : "+l"(a0) : "l"(wD.x), "l"(sv2[6][0]));
            asm("fma.rn.f32x2 %0, %1, %2, %0;" : "+l"(a1) : "l"(wD.x), "l"(sv2[6][1]));
            asm("fma.rn.f32x2 %0, %1, %2, %0;" : "+l"(a0) : "l"(wD.y), "l"(sv2[7][0]));
            asm("fma.rn.f32x2 %0, %1, %2, %0;" : "+l"(a1) : "l"(wD.y), "l"(sv2[7][1]));
            asm("fma.rn.f32x2 %0, %1, %2, %0;" : "+l"(a0) : "l"(wE),   "l"(sv2[8][0]));
            asm("fma.rn.f32x2 %0, %1, %2, %0;" : "+l"(a1) : "l"(wE),   "l"(sv2[8][1]));

            float4 out;
            asm("mov.b64 {%0, %1}, %2;" : "=f"(out.x), "=f"(out.y) : "l"(a0));
            asm("mov.b64 {%0, %1}, %2;" : "=f"(out.z), "=f"(out.w) : "l"(a1));
            __stcs(yp + (size_t)oo * 16 * (HW / 4), out);
        }
    }

    // ============ Reset pipeline state for the next graph replay ============
    __syncthreads();
    if (tid == 0) {
        int d = atomicAdd(&g_dep, 1);
        if (d == NBLK - 1) {                             // last block out resets
            g_t1 = 0; g_t2 = 0; g_weff_cnt = 0; g_dep = 0;
#pragma unroll
            for (int i = 0; i < B_; i++) g_ready[i] = 0;
            __threadfence();
        }
    }
}

// ---------------------------------------------------------------------------
extern "C" void kernel_launch(void* const* d_in, const int* in_sizes, int n_in,
                              void* d_out, int out_size) {
    const float* x = (const float*)d_in[0];
    const float* w = (const float*)d_in[1];
    if (n_in >= 2 && in_sizes[0] == COUT * COUT) {       // order safety
        const float* t = x; x = w; w = t;
    }
    float* y = (float*)d_out;

    shiftconv_fused<<<NBLK, 256>>>((const float4*)x, w, y);
}

// round 16
// speedup vs baseline: 1.0781x; 1.0781x over previous
#include <cuda_runtime.h>
#include <cstddef>

// Problem constants (fixed by setup_inputs)
#define B_   32
#define CIN  256
#define COUT 512
#define H_   64
#define W_   64
#define HW   (H_*W_)          // 4096
#define GROUPS 9
#define IN_CPG 28             // 252 channels used, 28 per group
#define OUT_CPG 56            // 504 channels, 56 per group; 504..511 -> group 4

#define NBLK 608              // 4/SM x 152 (GB300); excess blocks drain & exit safely
#define WEFF_TASKS 576        // warp per (o,g), 8 warps per task, tasks [0, 576)
#define GSUM_TASKS 1152       // tasks [576, 1728), batch-major (36 per batch)
#define PH1_TASKS  (WEFF_TASKS + GSUM_TASKS)
#define TASKS_PER_BATCH 36    // 9 groups x 4 quarter-planes
#define PW_TASKS (B_ * H_)    // 2048 whole-row tasks (R14-proven granularity)

#define WSTRIDE 20            // floats per o-row in w_dup2 (9 dup pairs + pad, 80B)

// Scratch + pipeline state (all zero-init; reset by last departer each launch)
__device__ float g_s[B_ * GROUPS * HW];
__device__ float g_we[COUT * GROUPS];
__device__ int g_t1, g_t2, g_weff_cnt, g_dep;
__device__ int g_ready[B_];

__global__ __launch_bounds__(256, 4) void shiftconv_fused(
    const float4* __restrict__ x4, const float* __restrict__ wp,
    float* __restrict__ y)
{
    __shared__ float w_dup2[COUT * WSTRIDE];             // 40,960 B
    __shared__ float s_sh[GROUPS][W_ + 2];               // 2,376 B
    __shared__ int task_sh;
    const int tid = threadIdx.x;

    // ================= Phase 1: pop prep tasks =================
    for (;;) {
        if (tid == 0) task_sh = atomicAdd(&g_t1, 1);
        __syncthreads();
        const int t = task_sh;
        __syncthreads();                                 // protect task_sh reuse
        if (t >= PH1_TASKS) break;

        if (t < WEFF_TASKS) {
            // W_eff: 8 warps per task, warp per (o,g), shuffle reduce
            const int warp = t * 8 + (tid >> 5);
            const int lane = tid & 31;
            const int o = warp / GROUPS, g = warp % GROUPS;
            const float* row = wp + (size_t)o * COUT;
            float s = 0.f;
            if (lane < IN_CPG)
                s = row[g * OUT_CPG + lane] + row[g * OUT_CPG + 28 + lane];
            if (g == 4 && lane < 8)
                s += row[504 + lane];
#pragma unroll
            for (int off = 16; off > 0; off >>= 1)
                s += __shfl_xor_sync(0xffffffffu, s, off);
            if (lane == 0) g_we[warp] = s;
            __threadfence();                             // release
            __syncthreads();
            if (tid == 0) atomicAdd(&g_weff_cnt, 1);
        } else {
            // gsum quarter-plane: j in [0,1152), one (b,g) quarter each
            const int j   = t - WEFF_TASKS;
            const int idx = j * 256 + tid;
            const int hw4 = idx & (HW / 4 - 1);
            const int tt  = idx >> 10;                   // b*9+g
            const int b = tt / GROUPS, g = tt % GROUPS;
            const float4* p = x4 + ((size_t)(b * CIN + g * IN_CPG) << 10) + hw4;
            float4 a = make_float4(0.f, 0.f, 0.f, 0.f);
#pragma unroll
            for (int k = 0; k < IN_CPG; k++) {
                float4 v = __ldcs(p + ((size_t)k << 10));
                a.x += v.x; a.y += v.y; a.z += v.z; a.w += v.w;
            }
            reinterpret_cast<float4*>(g_s)[(size_t)tt * (HW / 4) + hw4] = a;
            __threadfence();                             // release
            __syncthreads();
            if (tid == 0) atomicAdd(&g_ready[j / TASKS_PER_BATCH], 1);
        }
    }

    // ============ Transition: wait weff, stage weights once ============
    if (tid == 0) {
        while (*(volatile int*)&g_weff_cnt < WEFF_TASKS) __nanosleep(64);
    }
    __syncthreads();
    __threadfence();                                     // acquire side
    for (int i = tid; i < COUT * GROUPS; i += 256) {
        int o = i / GROUPS, g = i - o * GROUPS;
        float v = __ldcg(&g_we[i]);                      // L2 read (no L1 window)
        w_dup2[o * WSTRIDE + 2 * g]     = v;
        w_dup2[o * WSTRIDE + 2 * g + 1] = v;
    }
    for (int i = tid; i < GROUPS * (W_ + 2); i += 256)   // halo zeros
        (&s_sh[0][0])[i] = 0.f;
    // pop-sync below covers visibility of w_dup2/s_sh before first use

    const int w0  = (tid & 15) * 4;
    const int och = tid >> 4;                            // 0..15

    // ================= Phase 2: pop pw whole-row tasks =================
    for (;;) {
        if (tid == 0) {
            int r = atomicAdd(&g_t2, 1);
            if (r < PW_TASKS) {
                int rb = r >> 6;
                while (*(volatile int*)&g_ready[rb] < TASKS_PER_BATCH)
                    __nanosleep(64);
            }
            task_sh = r;
        }
        __syncthreads();
        const int r = task_sh;
        __syncthreads();                                 // protect task_sh + s_sh reuse
        if (r >= PW_TASKS) break;
        const int b = r >> 6, h = r & 63;
        __threadfence();                                 // acquire for g_s

        // stage s rows: VECTORIZED float4 global loads (144 total -> single
        // pass, 1 long-scoreboard LDG per thread instead of 2.25). Scatter
        // with 4 scalar STS (halo +1 offset forbids vector STS). Zeros for OOB.
        {
            int i = tid;
            if (i < GROUPS * (W_ / 4)) {                 // 144 tasks of 256 threads
                int g = i >> 4, wc4 = i & 15;
                int hp = h + g / 3 - 1;
                float4 v = make_float4(0.f, 0.f, 0.f, 0.f);
                if ((unsigned)hp < (unsigned)H_)
                    v = __ldcg(reinterpret_cast<const float4*>(
                        &g_s[((size_t)(b * GROUPS + g) << 12) + (hp << 6)]) + wc4);
                float* dst = &s_sh[g][wc4 * 4 + 1];
                dst[0] = v.x; dst[1] = v.y; dst[2] = v.z; dst[3] = v.w;
            }
        }
        __syncthreads();

        // pack shifted s pixel pairs: idx w0+dx+1 = w0 + g%3
        unsigned long long sv2[GROUPS][2];
#pragma unroll
        for (int g = 0; g < GROUPS; g++) {
            const float* rr = &s_sh[g][w0 + (g % 3)];
            asm("mov.b64 %0, {%1, %2};" : "=l"(sv2[g][0]) : "f"(rr[0]), "f"(rr[1]));
            asm("mov.b64 %0, {%1, %2};" : "=l"(sv2[g][1]) : "f"(rr[2]), "f"(rr[3]));
        }

        float4* yp = reinterpret_cast<float4*>(
            y + ((size_t)b * COUT + och) * HW + h * W_ + w0);
#pragma unroll 4
        for (int oo = 0; oo < 32; oo++) {
            const int o = oo * 16 + och;
            const float* wrow = &w_dup2[o * WSTRIDE];
            ulonglong2 wA = *reinterpret_cast<const ulonglong2*>(wrow);      // g0,g1
            ulonglong2 wB = *reinterpret_cast<const ulonglong2*>(wrow + 4);  // g2,g3
            ulonglong2 wC = *reinterpret_cast<const ulonglong2*>(wrow + 8);  // g4,g5
            ulonglong2 wD = *reinterpret_cast<const ulonglong2*>(wrow + 12); // g6,g7
            unsigned long long wE =
                *reinterpret_cast<const unsigned long long*>(wrow + 16);     // g8

            unsigned long long a0 = 0ull, a1 = 0ull;
            asm("fma.rn.f32x2 %0, %1, %2, %0;" : "+l"(a0) : "l"(wA.x), "l"(sv2[0][0]));
            asm("fma.rn.f32x2 %0, %1, %2, %0;" : "+l"(a1) : "l"(wA.x), "l"(sv2[0][1]));
            asm("fma.rn.f32x2 %0, %1, %2, %0;" : "+l"(a0) : "l"(wA.y), "l"(sv2[1][0]));
            asm("fma.rn.f32x2 %0, %1, %2, %0;" : "+l"(a1) : "l"(wA.y), "l"(sv2[1][1]));
            asm("fma.rn.f32x2 %0, %1, %2, %0;" : "+l"(a0) : "l"(wB.x), "l"(sv2[2][0]));
            asm("fma.rn.f32x2 %0, %1, %2, %0;" : "+l"(a1) : "l"(wB.x), "l"(sv2[2][1]));
            asm("fma.rn.f32x2 %0, %1, %2, %0;" : "+l"(a0) : "l"(wB.y), "l"(sv2[3][0]));
            asm("fma.rn.f32x2 %0, %1, %2, %0;" : "+l"(a1) : "l"(wB.y), "l"(sv2[3][1]));
            asm("fma.rn.f32x2 %0, %1, %2, %0;" : "+l"(a0) : "l"(wC.x), "l"(sv2[4][0]));
            asm("fma.rn.f32x2 %0, %1, %2, %0;" : "+l"(a1) : "l"(wC.x), "l"(sv2[4][1]));
            asm("fma.rn.f32x2 %0, %1, %2, %0;" : "+l"(a0) : "l"(wC.y), "l"(sv2[5][0]));
            asm("fma.rn.f32x2 %0, %1, %2, %0;" : "+l"(a1) : "l"(wC.y), "l"(sv2[5][1]));
            asm("fma.rn.f32x2 %0, %1, %2, %0;" : "+l"(a0) : "l"(wD.x), "l"(sv2[6][0]));
            asm("fma.rn.f32x2 %0, %1, %2, %0;" : "+l"(a1) : "l"(wD.x), "l"(sv2[6][1]));
            asm("fma.rn.f32x2 %0, %1, %2, %0;" : "+l"(a0) : "l"(wD.y), "l"(sv2[7][0]));
            asm("fma.rn.f32x2 %0, %1, %2, %0;" : "+l"(a1) : "l"(wD.y), "l"(sv2[7][1]));
            asm("fma.rn.f32x2 %0, %1, %2, %0;" : "+l"(a0) : "l"(wE),   "l"(sv2[8][0]));
            asm("fma.rn.f32x2 %0, %1, %2, %0;" : "+l"(a1) : "l"(wE),   "l"(sv2[8][1]));

            float4 out;
            asm("mov.b64 {%0, %1}, %2;" : "=f"(out.x), "=f"(out.y) : "l"(a0));
            asm("mov.b64 {%0, %1}, %2;" : "=f"(out.z), "=f"(out.w) : "l"(a1));
            __stcs(yp + (size_t)oo * 16 * (HW / 4), out);
        }
    }

    // ============ Reset pipeline state for the next graph replay ============
    __syncthreads();
    if (tid == 0) {
        int d = atomicAdd(&g_dep, 1);
        if (d == NBLK - 1) {                             // last block out resets
            g_t1 = 0; g_t2 = 0; g_weff_cnt = 0; g_dep = 0;
#pragma unroll
            for (int i = 0; i < B_; i++) g_ready[i] = 0;
            __threadfence();
        }
    }
}

// ---------------------------------------------------------------------------
extern "C" void kernel_launch(void* const* d_in, const int* in_sizes, int n_in,
                              void* d_out, int out_size) {
    const float* x = (const float*)d_in[0];
    const float* w = (const float*)d_in[1];
    if (n_in >= 2 && in_sizes[0] == COUT * COUT) {       // order safety
        const float* t = x; x = w; w = t;
    }
    float* y = (float*)d_out;

    shiftconv_fused<<<NBLK, 256>>>((const float4*)x, w, y);
}

// round 17
// speedup vs baseline: 1.1079x; 1.0276x over previous
#include <cuda_runtime.h>
#include <cstddef>

// Problem constants (fixed by setup_inputs)
#define B_   32
#define CIN  256
#define COUT 512
#define H_   64
#define W_   64
#define HW   (H_*W_)          // 4096
#define GROUPS 9
#define IN_CPG 28             // 252 channels used, 28 per group
#define OUT_CPG 56            // 504 channels, 56 per group; 504..511 -> group 4

#define NBLK 608              // 4/SM x 152 (GB300)
#define CONS_BLOCKS 152       // dedicated consumers (skip phase 1): last 152 blocks
#define PROD_BLOCKS (NBLK - CONS_BLOCKS)   // 456 producers
#define WEFF_TASKS 576        // warp per (o,g), 8 warps per task, tasks [0, 576)
#define GSUM_TASKS 1152       // tasks [576, 1728), batch-major (36 per batch)
#define PH1_TASKS  (WEFF_TASKS + GSUM_TASKS)
#define TASKS_PER_BATCH 36    // 9 groups x 4 quarter-planes
#define PW_TASKS (B_ * H_)    // 2048 whole-row tasks (R14/R16-proven granularity)

#define WSTRIDE 20            // floats per o-row in w_dup2 (9 dup pairs + pad, 80B)

// Scratch + pipeline state (all zero-init; reset by last departer each launch)
__device__ float g_s[B_ * GROUPS * HW];
__device__ float g_we[COUT * GROUPS];
__device__ int g_t1, g_t2, g_weff_cnt, g_dep;
__device__ int g_ready[B_];

__global__ __launch_bounds__(256, 4) void shiftconv_fused(
    const float4* __restrict__ x4, const float* __restrict__ wp,
    float* __restrict__ y)
{
    __shared__ float w_dup2[COUT * WSTRIDE];             // 40,960 B
    __shared__ float s_sh[GROUPS][W_ + 2];               // 2,376 B
    __shared__ int task_sh;
    const int tid = threadIdx.x;

    // ====== Phase 1 (PRODUCERS ONLY): pop prep tasks. Consumers skip. ======
    if (blockIdx.x < PROD_BLOCKS)
    for (;;) {
        if (tid == 0) task_sh = atomicAdd(&g_t1, 1);
        __syncthreads();
        const int t = task_sh;
        __syncthreads();                                 // protect task_sh reuse
        if (t >= PH1_TASKS) break;

        if (t < WEFF_TASKS) {
            // W_eff: 8 warps per task, warp per (o,g), shuffle reduce
            const int warp = t * 8 + (tid >> 5);
            const int lane = tid & 31;
            const int o = warp / GROUPS, g = warp % GROUPS;
            const float* row = wp + (size_t)o * COUT;
            float s = 0.f;
            if (lane < IN_CPG)
                s = row[g * OUT_CPG + lane] + row[g * OUT_CPG + 28 + lane];
            if (g == 4 && lane < 8)
                s += row[504 + lane];
#pragma unroll
            for (int off = 16; off > 0; off >>= 1)
                s += __shfl_xor_sync(0xffffffffu, s, off);
            if (lane == 0) g_we[warp] = s;
            __threadfence();                             // release
            __syncthreads();
            if (tid == 0) atomicAdd(&g_weff_cnt, 1);
        } else {
            // gsum quarter-plane: j in [0,1152), one (b,g) quarter each
            const int j   = t - WEFF_TASKS;
            const int idx = j * 256 + tid;
            const int hw4 = idx & (HW / 4 - 1);
            const int tt  = idx >> 10;                   // b*9+g
            const int b = tt / GROUPS, g = tt % GROUPS;
            const float4* p = x4 + ((size_t)(b * CIN + g * IN_CPG) << 10) + hw4;
            float4 a = make_float4(0.f, 0.f, 0.f, 0.f);
#pragma unroll
            for (int k = 0; k < IN_CPG; k++) {
                float4 v = __ldcs(p + ((size_t)k << 10));
                a.x += v.x; a.y += v.y; a.z += v.z; a.w += v.w;
            }
            reinterpret_cast<float4*>(g_s)[(size_t)tt * (HW / 4) + hw4] = a;
            __threadfence();                             // release
            __syncthreads();
            if (tid == 0) atomicAdd(&g_ready[j / TASKS_PER_BATCH], 1);
        }
    }

    // ============ Transition: wait weff, stage weights once ============
    if (tid == 0) {
        while (*(volatile int*)&g_weff_cnt < WEFF_TASKS) __nanosleep(64);
    }
    __syncthreads();
    __threadfence();                                     // acquire side
    for (int i = tid; i < COUT * GROUPS; i += 256) {
        int o = i / GROUPS, g = i - o * GROUPS;
        float v = __ldcg(&g_we[i]);                      // L2 read (no L1 window)
        w_dup2[o * WSTRIDE + 2 * g]     = v;
        w_dup2[o * WSTRIDE + 2 * g + 1] = v;
    }
    for (int i = tid; i < GROUPS * (W_ + 2); i += 256)   // halo zeros
        (&s_sh[0][0])[i] = 0.f;
    // pop-sync below covers visibility of w_dup2/s_sh before first use

    const int w0  = (tid & 15) * 4;
    const int och = tid >> 4;                            // 0..15

    // ================= Phase 2: pop pw whole-row tasks =================
    for (;;) {
        if (tid == 0) {
            int r = atomicAdd(&g_t2, 1);
            if (r < PW_TASKS) {
                int rb = r >> 6;
                while (*(volatile int*)&g_ready[rb] < TASKS_PER_BATCH)
                    __nanosleep(64);
            }
            task_sh = r;
        }
        __syncthreads();
        const int r = task_sh;
        __syncthreads();                                 // protect task_sh + s_sh reuse
        if (r >= PW_TASKS) break;
        const int b = r >> 6, h = r & 63;
        __threadfence();                                 // acquire for g_s

        // stage s rows: vectorized float4 L2 loads (144 -> single pass),
        // scatter 4 scalar STS (halo +1 forbids vector STS). Zeros for OOB.
        {
            int i = tid;
            if (i < GROUPS * (W_ / 4)) {                 // 144 of 256 threads
                int g = i >> 4, wc4 = i & 15;
                int hp = h + g / 3 - 1;
                float4 v = make_float4(0.f, 0.f, 0.f, 0.f);
                if ((unsigned)hp < (unsigned)H_)
                    v = __ldcg(reinterpret_cast<const float4*>(
                        &g_s[((size_t)(b * GROUPS + g) << 12) + (hp << 6)]) + wc4);
                float* dst = &s_sh[g][wc4 * 4 + 1];
                dst[0] = v.x; dst[1] = v.y; dst[2] = v.z; dst[3] = v.w;
            }
        }
        __syncthreads();

        // pack shifted s pixel pairs: idx w0+dx+1 = w0 + g%3
        unsigned long long sv2[GROUPS][2];
#pragma unroll
        for (int g = 0; g < GROUPS; g++) {
            const float* rr = &s_sh[g][w0 + (g % 3)];
            asm("mov.b64 %0, {%1, %2};" : "=l"(sv2[g][0]) : "f"(rr[0]), "f"(rr[1]));
            asm("mov.b64 %0, {%1, %2};" : "=l"(sv2[g][1]) : "f"(rr[2]), "f"(rr[3]));
        }

        float4* yp = reinterpret_cast<float4*>(
            y + ((size_t)b * COUT + och) * HW + h * W_ + w0);
#pragma unroll 4
        for (int oo = 0; oo < 32; oo++) {
            const int o = oo * 16 + och;
            const float* wrow = &w_dup2[o * WSTRIDE];
            ulonglong2 wA = *reinterpret_cast<const ulonglong2*>(wrow);      // g0,g1
            ulonglong2 wB = *reinterpret_cast<const ulonglong2*>(wrow + 4);  // g2,g3
            ulonglong2 wC = *reinterpret_cast<const ulonglong2*>(wrow + 8);  // g4,g5
            ulonglong2 wD = *reinterpret_cast<const ulonglong2*>(wrow + 12); // g6,g7
            unsigned long long wE =
                *reinterpret_cast<const unsigned long long*>(wrow + 16);     // g8

            unsigned long long a0 = 0ull, a1 = 0ull;
            asm("fma.rn.f32x2 %0, %1, %2, %0;" : "+l"(a0) : "l"(wA.x), "l"(sv2[0][0]));
            asm("fma.rn.f32x2 %0, %1, %2, %0;" : "+l"(a1) : "l"(wA.x), "l"(sv2[0][1]));
            asm("fma.rn.f32x2 %0, %1, %2, %0;" : "+l"(a0) : "l"(wA.y), "l"(sv2[1][0]));
            asm("fma.rn.f32x2 %0, %1, %2, %0;" : "+l"(a1) : "l"(wA.y), "l"(sv2[1][1]));
            asm("fma.rn.f32x2 %0, %1, %2, %0;" : "+l"(a0) : "l"(wB.x), "l"(sv2[2][0]));
            asm("fma.rn.f32x2 %0, %1, %2, %0;" : "+l"(a1) : "l"(wB.x), "l"(sv2[2][1]));
            asm("fma.rn.f32x2 %0, %1, %2, %0;" : "+l"(a0) : "l"(wB.y), "l"(sv2[3][0]));
            asm("fma.rn.f32x2 %0, %1, %2, %0;" : "+l"(a1) : "l"(wB.y), "l"(sv2[3][1]));
            asm("fma.rn.f32x2 %0, %1, %2, %0;" : "+l"(a0) : "l"(wC.x), "l"(sv2[4][0]));
            asm("fma.rn.f32x2 %0, %1, %2, %0;" : "+l"(a1) : "l"(wC.x), "l"(sv2[4][1]));
            asm("fma.rn.f32x2 %0, %1, %2, %0;" : "+l"(a0) : "l"(wC.y), "l"(sv2[5][0]));
            asm("fma.rn.f32x2 %0, %1, %2, %0;" : "+l"(a1) : "l"(wC.y), "l"(sv2[5][1]));
            asm("fma.rn.f32x2 %0, %1, %2, %0;" : "+l"(a0) : "l"(wD.x), "l"(sv2[6][0]));
            asm("fma.rn.f32x2 %0, %1, %2, %0;" : "+l"(a1) : "l"(wD.x), "l"(sv2[6][1]));
            asm("fma.rn.f32x2 %0, %1, %2, %0;" : "+l"(a0) : "l"(wD.y), "l"(sv2[7][0]));
            asm("fma.rn.f32x2 %0, %1, %2, %0;" : "+l"(a1) : "l"(wD.y), "l"(sv2[7][1]));
            asm("fma.rn.f32x2 %0, %1, %2, %0;" : "+l"(a0) : "l"(wE),   "l"(sv2[8][0]));
            asm("fma.rn.f32x2 %0, %1, %2, %0;" : "+l"(a1) : "l"(wE),   "l"(sv2[8][1]));

            float4 out;
            asm("mov.b64 {%0, %1}, %2;" : "=f"(out.x), "=f"(out.y) : "l"(a0));
            asm("mov.b64 {%0, %1}, %2;" : "=f"(out.z), "=f"(out.w) : "l"(a1));
            __stcs(yp + (size_t)oo * 16 * (HW / 4), out);
        }
    }

    // ============ Reset pipeline state for the next graph replay ============
    __syncthreads();
    if (tid == 0) {
        int d = atomicAdd(&g_dep, 1);
        if (d == NBLK - 1) {                             // last block out resets
            g_t1 = 0; g_t2 = 0; g_weff_cnt = 0; g_dep = 0;
#pragma unroll
            for (int i = 0; i < B_; i++) g_ready[i] = 0;
            __threadfence();
        }
    }
}

// ---------------------------------------------------------------------------
extern "C" void kernel_launch(void* const* d_in, const int* in_sizes, int n_in,
                              void* d_out, int out_size) {
    const float* x = (const float*)d_in[0];
    const float* w = (const float*)d_in[1];
    if (n_in >= 2 && in_sizes[0] == COUT * COUT) {       // order safety
        const float* t = x; x = w; w = t;
    }
    float* y = (float*)d_out;

    shiftconv_fused<<<NBLK, 256>>>((const float4*)x, w, y);
}